// round 1
// baseline (speedup 1.0000x reference)
#include <cuda_runtime.h>
#include <cuda_bf16.h>
#include <math.h>

// Problem constants
#define B_  2
#define S_  2048
#define D_  2048
#define H_  16
#define HD_ 128
#define M_  (B_ * S_)          // 4096
#define TOT_ (B_ * H_ * S_ * HD_)  // 8388608

// ---------------------------------------------------------------------------
// Scratch (no cudaMalloc allowed)
// ---------------------------------------------------------------------------
__device__ float g_qraw[(size_t)M_ * D_];
__device__ float g_kraw[(size_t)M_ * D_];
__device__ float g_vraw[(size_t)M_ * D_];
__device__ float g_Q[(size_t)TOT_];
__device__ float g_K[(size_t)TOT_];
__device__ float g_V[(size_t)TOT_];
__device__ float g_O[(size_t)TOT_];
__device__ float g_Ot[(size_t)M_ * D_];

// ---------------------------------------------------------------------------
// SGEMM: C[M,N] = A[M,K] @ B[N,K]^T   (both row-major, "A·B-transpose")
// 128x128 block tile, BK=16, 256 threads, 8x8 per thread.
// ---------------------------------------------------------------------------
#define BM 128
#define BN 128
#define BK 16

__global__ void __launch_bounds__(256)
gemm_abt(const float* __restrict__ A, const float* __restrict__ Bw,
         float* __restrict__ C, int Mdim, int Ndim, int Kdim)
{
    __shared__ float As[BK][BM + 4];
    __shared__ float Bs[BK][BN + 4];

    const int tid = threadIdx.x;
    const int tx = tid & 15;        // 0..15
    const int ty = tid >> 4;        // 0..15
    const int m0 = blockIdx.y * BM;
    const int n0 = blockIdx.x * BN;

    float acc[8][8];
#pragma unroll
    for (int i = 0; i < 8; i++)
#pragma unroll
        for (int j = 0; j < 8; j++) acc[i][j] = 0.f;

    for (int kt = 0; kt < Kdim; kt += BK) {
        // Load A tile (128 rows x 16 cols) transposed into As[k][m]
#pragma unroll
        for (int it = 0; it < 2; it++) {
            int slot = tid + it * 256;          // 0..511
            int row = slot >> 2;
            int c4 = (slot & 3) * 4;
            float4 v = *(const float4*)&A[(size_t)(m0 + row) * Kdim + kt + c4];
            As[c4 + 0][row] = v.x;
            As[c4 + 1][row] = v.y;
            As[c4 + 2][row] = v.z;
            As[c4 + 3][row] = v.w;
        }
        // Load B tile (weights, [N,K] row-major) transposed into Bs[k][n]
#pragma unroll
        for (int it = 0; it < 2; it++) {
            int slot = tid + it * 256;
            int row = slot >> 2;
            int c4 = (slot & 3) * 4;
            float4 v = *(const float4*)&Bw[(size_t)(n0 + row) * Kdim + kt + c4];
            Bs[c4 + 0][row] = v.x;
            Bs[c4 + 1][row] = v.y;
            Bs[c4 + 2][row] = v.z;
            Bs[c4 + 3][row] = v.w;
        }
        __syncthreads();

#pragma unroll
        for (int kk = 0; kk < BK; kk++) {
            float a[8], b[8];
            *(float4*)&a[0] = *(const float4*)&As[kk][ty * 8];
            *(float4*)&a[4] = *(const float4*)&As[kk][ty * 8 + 4];
            *(float4*)&b[0] = *(const float4*)&Bs[kk][tx * 8];
            *(float4*)&b[4] = *(const float4*)&Bs[kk][tx * 8 + 4];
#pragma unroll
            for (int i = 0; i < 8; i++)
#pragma unroll
                for (int j = 0; j < 8; j++)
                    acc[i][j] = fmaf(a[i], b[j], acc[i][j]);
        }
        __syncthreads();
    }

#pragma unroll
    for (int i = 0; i < 8; i++) {
        size_t r = (size_t)(m0 + ty * 8 + i) * Ndim + n0 + tx * 8;
        float4 v0 = make_float4(acc[i][0], acc[i][1], acc[i][2], acc[i][3]);
        float4 v1 = make_float4(acc[i][4], acc[i][5], acc[i][6], acc[i][7]);
        *(float4*)&C[r] = v0;
        *(float4*)&C[r + 4] = v1;
    }
}

// ---------------------------------------------------------------------------
// RoPE + pack [B,S,H*hd] raw projections -> [B,H,S,hd] Q,K (roped) and V
// ---------------------------------------------------------------------------
__global__ void rope_pack(const float* __restrict__ qraw,
                          const float* __restrict__ kraw,
                          const float* __restrict__ vraw,
                          float* __restrict__ Q, float* __restrict__ K,
                          float* __restrict__ V)
{
    int i = blockIdx.x * 256 + threadIdx.x;
    if (i >= TOT_) return;
    int d = i & (HD_ - 1);
    int s = (i >> 7) & (S_ - 1);
    int h = (i >> 18) & (H_ - 1);
    int b = i >> 22;

    size_t raw = (size_t)(b * S_ + s) * D_ + h * HD_ + d;
    int dp = (d < 64) ? d + 64 : d - 64;
    size_t rawp = raw + (dp - d);

    // inv_freq = 10000^(-(d mod 64)/64); double-precision then round, to track
    // the reference's fp32 value as closely as possible.
    int j = d & 63;
    float inv = (float)exp(-(double)j * 0.14391156831212788); // ln(10000)/64
    float ang = (float)s * inv;
    float sn, cs;
    sincosf(ang, &sn, &cs);

    float qv = qraw[raw], qp = qraw[rawp];
    float kv = kraw[raw], kp = kraw[rawp];
    float rq = (d < 64) ? -qp : qp;
    float rk = (d < 64) ? -kp : kp;

    Q[i] = fmaf(rq, sn, qv * cs);
    K[i] = fmaf(rk, sn, kv * cs);
    V[i] = vraw[raw];
}

// ---------------------------------------------------------------------------
// Flash attention, fp32, causal. One block = one (b*h, 64-row q tile).
// ---------------------------------------------------------------------------
struct SmemAttn {
    float Qs[128][68];   // [k][r], Q^T, scaled
    float Ks[128][68];   // [k][c], K^T
    float Vs[64][128];   // [c][d]
    float Ss[64][68];    // scores / probs
    float mrow[64];
    float lrow[64];
    float corr[64];
};

__global__ void __launch_bounds__(256)
flash_attn(const float* __restrict__ Qg, const float* __restrict__ Kg,
           const float* __restrict__ Vg, float* __restrict__ Og)
{
    extern __shared__ char smem_raw[];
    SmemAttn& sm = *reinterpret_cast<SmemAttn*>(smem_raw);

    const int tid = threadIdx.x;
    const int tx = tid & 15;
    const int ty = tid >> 4;
    const int bh = blockIdx.y;
    // heavy tiles (large q0 => more kv tiles) scheduled first
    const int q0 = (gridDim.x - 1 - blockIdx.x) * 64;

    const float* Qb = Qg + (size_t)bh * S_ * HD_;
    const float* Kb = Kg + (size_t)bh * S_ * HD_;
    const float* Vb = Vg + (size_t)bh * S_ * HD_;
    float* Ob       = Og + (size_t)bh * S_ * HD_;

    const float scale = 0.08838834764831845f; // 128^-0.5

    // Load Q tile transposed (scaled)
    for (int i = tid; i < 64 * 32; i += 256) {
        int r = i >> 5;
        int c4 = (i & 31) * 4;
        float4 v = *(const float4*)&Qb[(size_t)(q0 + r) * HD_ + c4];
        sm.Qs[c4 + 0][r] = v.x * scale;
        sm.Qs[c4 + 1][r] = v.y * scale;
        sm.Qs[c4 + 2][r] = v.z * scale;
        sm.Qs[c4 + 3][r] = v.w * scale;
    }
    if (tid < 64) {
        sm.mrow[tid] = -1e30f;
        sm.lrow[tid] = 0.f;
    }

    float o[4][8];
#pragma unroll
    for (int i = 0; i < 4; i++)
#pragma unroll
        for (int j = 0; j < 8; j++) o[i][j] = 0.f;

    const int ntiles = q0 / 64 + 1;
    for (int kt = 0; kt < ntiles; kt++) {
        const int k0 = kt * 64;

        // Load K (transposed) and V (direct)
        for (int i = tid; i < 64 * 32; i += 256) {
            int c = i >> 5;
            int c4 = (i & 31) * 4;
            float4 kv4 = *(const float4*)&Kb[(size_t)(k0 + c) * HD_ + c4];
            sm.Ks[c4 + 0][c] = kv4.x;
            sm.Ks[c4 + 1][c] = kv4.y;
            sm.Ks[c4 + 2][c] = kv4.z;
            sm.Ks[c4 + 3][c] = kv4.w;
            float4 vv4 = *(const float4*)&Vb[(size_t)(k0 + c) * HD_ + c4];
            *(float4*)&sm.Vs[c][c4] = vv4;
        }
        __syncthreads();

        // Scores: 4x4 per thread over 64x64
        float sc[4][4];
#pragma unroll
        for (int i = 0; i < 4; i++)
#pragma unroll
            for (int j = 0; j < 4; j++) sc[i][j] = 0.f;

#pragma unroll 8
        for (int k = 0; k < 128; k++) {
            float4 qa = *(const float4*)&sm.Qs[k][ty * 4];
            float4 kb = *(const float4*)&sm.Ks[k][tx * 4];
            float qq[4] = {qa.x, qa.y, qa.z, qa.w};
            float kk2[4] = {kb.x, kb.y, kb.z, kb.w};
#pragma unroll
            for (int i = 0; i < 4; i++)
#pragma unroll
                for (int j = 0; j < 4; j++)
                    sc[i][j] = fmaf(qq[i], kk2[j], sc[i][j]);
        }
        // causal mask + store
#pragma unroll
        for (int i = 0; i < 4; i++) {
            int gq = q0 + ty * 4 + i;
#pragma unroll
            for (int j = 0; j < 4; j++) {
                int gk = k0 + tx * 4 + j;
                sm.Ss[ty * 4 + i][tx * 4 + j] = (gk <= gq) ? sc[i][j] : -1e30f;
            }
        }
        __syncthreads();

        // Online softmax: 4 threads per row, 16 cols each
        {
            int r = tid >> 2;
            int q = tid & 3;
            float mx = -1e30f;
#pragma unroll
            for (int cc = 0; cc < 16; cc++)
                mx = fmaxf(mx, sm.Ss[r][q * 16 + cc]);
            mx = fmaxf(mx, __shfl_xor_sync(0xffffffffu, mx, 1));
            mx = fmaxf(mx, __shfl_xor_sync(0xffffffffu, mx, 2));
            float m_old = sm.mrow[r];
            float m_new = fmaxf(m_old, mx);
            float ssum = 0.f;
#pragma unroll
            for (int cc = 0; cc < 16; cc++) {
                float p = __expf(sm.Ss[r][q * 16 + cc] - m_new);
                sm.Ss[r][q * 16 + cc] = p;
                ssum += p;
            }
            ssum += __shfl_xor_sync(0xffffffffu, ssum, 1);
            ssum += __shfl_xor_sync(0xffffffffu, ssum, 2);
            if (q == 0) {
                float cr = __expf(m_old - m_new);
                sm.lrow[r] = sm.lrow[r] * cr + ssum;
                sm.mrow[r] = m_new;
                sm.corr[r] = cr;
            }
        }
        __syncthreads();

        // O update: rows ty*4+i, cols tx*8..tx*8+7
#pragma unroll
        for (int i = 0; i < 4; i++) {
            float cr = sm.corr[ty * 4 + i];
#pragma unroll
            for (int j = 0; j < 8; j++) o[i][j] *= cr;
        }
#pragma unroll 4
        for (int c = 0; c < 64; c++) {
            float4 v0 = *(const float4*)&sm.Vs[c][tx * 8];
            float4 v1 = *(const float4*)&sm.Vs[c][tx * 8 + 4];
            float vv[8] = {v0.x, v0.y, v0.z, v0.w, v1.x, v1.y, v1.z, v1.w};
#pragma unroll
            for (int i = 0; i < 4; i++) {
                float p = sm.Ss[ty * 4 + i][c];
#pragma unroll
                for (int j = 0; j < 8; j++)
                    o[i][j] = fmaf(p, vv[j], o[i][j]);
            }
        }
        __syncthreads();
    }

    // Normalize and write out
#pragma unroll
    for (int i = 0; i < 4; i++) {
        float invl = 1.f / sm.lrow[ty * 4 + i];
        size_t off = (size_t)(q0 + ty * 4 + i) * HD_ + tx * 8;
        float4 w0 = make_float4(o[i][0] * invl, o[i][1] * invl,
                                o[i][2] * invl, o[i][3] * invl);
        float4 w1 = make_float4(o[i][4] * invl, o[i][5] * invl,
                                o[i][6] * invl, o[i][7] * invl);
        *(float4*)&Ob[off] = w0;
        *(float4*)&Ob[off + 4] = w1;
    }
}

// ---------------------------------------------------------------------------
// O [B,H,S,hd] -> Ot [B*S, D]
// ---------------------------------------------------------------------------
__global__ void transpose_O(const float* __restrict__ O, float* __restrict__ Ot)
{
    int i = blockIdx.x * 256 + threadIdx.x;
    if (i >= TOT_) return;
    int n = i & (D_ - 1);
    int m = i >> 11;
    int d = n & (HD_ - 1);
    int h = n >> 7;
    int s = m & (S_ - 1);
    int b = m >> 11;
    Ot[i] = O[(((size_t)(b * H_ + h) * S_ + s) << 7) + d];
}

// ---------------------------------------------------------------------------
// Launch
// ---------------------------------------------------------------------------
extern "C" void kernel_launch(void* const* d_in, const int* in_sizes, int n_in,
                              void* d_out, int out_size)
{
    const float* x  = (const float*)d_in[0];
    const float* Wq = (const float*)d_in[1];
    const float* Wk = (const float*)d_in[2];
    const float* Wv = (const float*)d_in[3];
    const float* Wo = (const float*)d_in[4];
    float* out = (float*)d_out;

    (void)in_sizes; (void)n_in; (void)out_size;

    dim3 gg(D_ / BN, M_ / BM);

    gemm_abt<<<gg, 256>>>(x, Wq, g_qraw, M_, D_, D_);
    gemm_abt<<<gg, 256>>>(x, Wk, g_kraw, M_, D_, D_);
    gemm_abt<<<gg, 256>>>(x, Wv, g_vraw, M_, D_, D_);

    rope_pack<<<TOT_ / 256, 256>>>(g_qraw, g_kraw, g_vraw, g_Q, g_K, g_V);

    cudaFuncSetAttribute(flash_attn, cudaFuncAttributeMaxDynamicSharedMemorySize,
                         (int)sizeof(SmemAttn));
    flash_attn<<<dim3(S_ / 64, B_ * H_), 256, sizeof(SmemAttn)>>>(g_Q, g_K, g_V, g_O);

    transpose_O<<<TOT_ / 256, 256>>>(g_O, g_Ot);

    gemm_abt<<<gg, 256>>>(g_Ot, Wo, out, M_, D_, D_);
}